// round 6
// baseline (speedup 1.0000x reference)
#include <cuda_runtime.h>
#include <cuda_bf16.h>
#include <cstdint>

#define M_DIM 64
#define K_DIM 8192
#define N_DIM 8192
#define KBLK  16
#define KSPLIT 8
#define KRANGE (K_DIM / KSPLIT)   /* 1024 */
#define KC     32
#define NT     64                 /* n-tile per CTA */
#define THREADS 256

__device__ float g_xd[M_DIM * K_DIM];                 // 2 MB: dequantized x (fp32)
__device__ float g_scratch8[KSPLIT * M_DIM * N_DIM];  // 16 MB: fp32 partial slabs

__constant__ float c_lut[16] = { 0.f, 0.5f, 1.f, 1.5f, 2.f, 3.f, 4.f, 6.f,
                                -0.f,-0.5f,-1.f,-1.5f,-2.f,-3.f,-4.f,-6.f};

// ---------------------------------------------------------------------------
// Kernel A: dequantize x -> fp32 (block scale folded; global scales applied
// at the end in finalize).
// ---------------------------------------------------------------------------
__global__ void prep_kernel(const int* __restrict__ x, const float* __restrict__ xs) {
    int idx = blockIdx.x * blockDim.x + threadIdx.x;
    if (idx >= M_DIM * K_DIM) return;
    int m = idx >> 13;            // idx / 8192
    int k = idx & (K_DIM - 1);
    g_xd[idx] = c_lut[x[idx] & 15] * xs[m * (K_DIM / KBLK) + (k >> 4)];
}

// ---------------------------------------------------------------------------
// Kernel B: exact fp32 GEMM. Grid (N/64, KSPLIT). CTA: 256 threads compute a
// 64m x 64n tile over a 1024-wide K range, writing a private slab.
// ---------------------------------------------------------------------------
__global__ void __launch_bounds__(THREADS)
gemm_oracle(const int* __restrict__ w, const float* __restrict__ wsc) {
    __shared__ float sx[M_DIM][KC + 1];   // x_dq tile [64 m][32 k]
    __shared__ float sw[NT][KC + 1];      // w_dq tile [64 n][32 k]

    const int tid = threadIdx.x;
    const int tx  = tid & 15;             // n sub-index
    const int ty  = tid >> 4;             // m sub-index
    const int n0  = blockIdx.x * NT;
    const int k0  = blockIdx.y * KRANGE;

    float acc[4][4];
    #pragma unroll
    for (int i = 0; i < 4; ++i)
        #pragma unroll
        for (int j = 0; j < 4; ++j) acc[i][j] = 0.f;

    for (int kc = 0; kc < KRANGE; kc += KC) {
        const int kb = k0 + kc;
        __syncthreads();                  // protect previous iteration's reads

        #pragma unroll
        for (int t = 0; t < 2; ++t) {
            int p   = tid + t * 256;
            int row = p >> 3;
            int q   = p & 7;

            float4 xv = *(const float4*)(g_xd + row * K_DIM + kb + q * 4);
            sx[row][q * 4 + 0] = xv.x;
            sx[row][q * 4 + 1] = xv.y;
            sx[row][q * 4 + 2] = xv.z;
            sx[row][q * 4 + 3] = xv.w;

            int4 cv = *(const int4*)(w + (long)(n0 + row) * K_DIM + kb + q * 4);
            float s = wsc[(n0 + row) * (K_DIM / KBLK) + ((kb + q * 4) >> 4)];
            sw[row][q * 4 + 0] = c_lut[cv.x & 15] * s;
            sw[row][q * 4 + 1] = c_lut[cv.y & 15] * s;
            sw[row][q * 4 + 2] = c_lut[cv.z & 15] * s;
            sw[row][q * 4 + 3] = c_lut[cv.w & 15] * s;
        }
        __syncthreads();

        #pragma unroll
        for (int k = 0; k < KC; ++k) {
            float a[4], b[4];
            #pragma unroll
            for (int i = 0; i < 4; ++i) a[i] = sx[ty + i * 16][k];
            #pragma unroll
            for (int j = 0; j < 4; ++j) b[j] = sw[tx + j * 16][k];
            #pragma unroll
            for (int i = 0; i < 4; ++i)
                #pragma unroll
                for (int j = 0; j < 4; ++j)
                    acc[i][j] = fmaf(a[i], b[j], acc[i][j]);
        }
    }

    float* S = g_scratch8 + blockIdx.y * (M_DIM * N_DIM);
    #pragma unroll
    for (int i = 0; i < 4; ++i) {
        const int m = ty + i * 16;
        #pragma unroll
        for (int j = 0; j < 4; ++j)
            S[m * N_DIM + n0 + tx + j * 16] = acc[i][j];
    }
}

// ---------------------------------------------------------------------------
// Kernel C: out (FLOAT32 buffer) = fp32( bf16( sum_slabs * gx*gw + bias[n] ) )
// The reference casts its fp32 result to bf16; the harness output buffer is
// fp32, so the expected values are bf16-representable fp32. Emulate the same
// round-to-nearest-even bf16 quantization, then store as fp32.
// ---------------------------------------------------------------------------
__global__ void finalize_kernel(const float* __restrict__ g1,
                                const float* __restrict__ g2,
                                const float* __restrict__ bias,
                                float* __restrict__ out) {
    int idx = blockIdx.x * blockDim.x + threadIdx.x;
    if (idx >= M_DIM * N_DIM) return;
    const float g = g1[0] * g2[0];
    const int n = idx & (N_DIM - 1);
    float s = 0.f;
    #pragma unroll
    for (int t = 0; t < KSPLIT; ++t)
        s += g_scratch8[idx + t * (M_DIM * N_DIM)];
    float v = fmaf(s, g, bias[n]);
    out[idx] = __bfloat162float(__float2bfloat16(v));   // bf16 RN, stored as fp32
}

// ---------------------------------------------------------------------------
// Inputs identified by element count (all distinct; byte-count fallback).
//   x=524288, x_scale=32768, weight=67108864, weight_scale=4194304, bias=8192
// The two size-1 global scales enter only as their product (order-free).
// ---------------------------------------------------------------------------
extern "C" void kernel_launch(void* const* d_in, const int* in_sizes, int n_in,
                              void* d_out, int out_size) {
    const int*   x    = nullptr;
    const float* xs   = nullptr;
    const int*   wgt  = nullptr;
    const float* wsc  = nullptr;
    const float* bias = nullptr;
    const float* gA   = nullptr;
    const float* gB   = nullptr;

    for (int pass = 0; pass < 2 && !wgt; ++pass) {
        const int mul = (pass == 0) ? 1 : 4;   // pass 1: sizes in bytes
        x = nullptr; xs = nullptr; wgt = nullptr; wsc = nullptr;
        bias = nullptr; gA = nullptr; gB = nullptr;
        for (int i = 0; i < n_in; ++i) {
            long sz = (long)in_sizes[i];
            if      (sz == (long)M_DIM * K_DIM * mul)          x    = (const int*)  d_in[i];
            else if (sz == (long)M_DIM * (K_DIM/KBLK) * mul)   xs   = (const float*)d_in[i];
            else if (sz == (long)N_DIM * K_DIM * mul)          wgt  = (const int*)  d_in[i];
            else if (sz == (long)N_DIM * (K_DIM/KBLK) * mul)   wsc  = (const float*)d_in[i];
            else if (sz == (long)N_DIM * mul)                  bias = (const float*)d_in[i];
            else if (sz == 1 * mul) { if (!gA) gA = (const float*)d_in[i];
                                      else     gB = (const float*)d_in[i]; }
        }
    }

    prep_kernel<<<(M_DIM * K_DIM) / 256, 256>>>(x, xs);
    gemm_oracle<<<dim3(N_DIM / NT, KSPLIT), THREADS>>>(wgt, wsc);
    finalize_kernel<<<(M_DIM * N_DIM) / 256, 256>>>(gA, gB, bias,
                                                    (float*)d_out);
}

// round 7
// speedup vs baseline: 2.0715x; 2.0715x over previous
#include <cuda_runtime.h>
#include <cuda_bf16.h>
#include <cstdint>

#define M_DIM 64
#define K_DIM 8192
#define N_DIM 8192
#define KBLK  16
#define NTILE 128
#define KSPLIT 4
#define KC    64
#define ITERS ((K_DIM / KSPLIT) / KC)   /* 32 */
#define THREADS 256
#define WSTRIDE 80   /* int8 row stride: 64 data + 16 pad -> conflict-free frags */

__device__ float  g_scratch4[KSPLIT * M_DIM * N_DIM];  // 8 MB fp32 partial slabs
__device__ int8_t g_xi8[M_DIM * K_DIM];                // 512 KB: x as int8 (2x values)

// 2x NVFP4 LUT as integers (sign folded): exact in int8.
__constant__ int c_ilut[16] = { 0, 1, 2, 3, 4, 6, 8, 12,
                                0,-1,-2,-3,-4,-6,-8,-12};

// ---------------------------------------------------------------------------
// Kernel A: x codes -> int8 (2x value). 4 codes per thread via shfl-LUT.
// ---------------------------------------------------------------------------
__global__ void prep_kernel(const int* __restrict__ x) {
    int t    = blockIdx.x * blockDim.x + threadIdx.x;   // < M*K/4
    int lane = threadIdx.x & 31;
    int ilut = c_ilut[lane & 15];
    int4 c = ((const int4*)x)[t];
    int v0 = __shfl_sync(0xffffffffu, ilut, c.x & 15);
    int v1 = __shfl_sync(0xffffffffu, ilut, c.y & 15);
    int v2 = __shfl_sync(0xffffffffu, ilut, c.z & 15);
    int v3 = __shfl_sync(0xffffffffu, ilut, c.w & 15);
    unsigned t01 = __byte_perm((unsigned)v0, (unsigned)v1, 0x0040);
    unsigned t23 = __byte_perm((unsigned)v2, (unsigned)v3, 0x0040);
    ((unsigned*)g_xi8)[t] = __byte_perm(t01, t23, 0x5410);
}

// ---------------------------------------------------------------------------
// Kernel B: exact int8 IMMA GEMM with per-16-block fp32 dequant.
// Grid (N/128, KSPLIT). CTA 256 thr (8 warps). Warp w: weight rows
// [w*16, w*16+16) x all 64 x-rows. One m16n8k16.s8 MMA = one scale block.
// ---------------------------------------------------------------------------
__global__ void __launch_bounds__(THREADS, 2)
gemm_kernel(const int* __restrict__ w, const float* __restrict__ wsc,
            const float* __restrict__ xsc) {
    __shared__ int8_t sW8[2][NTILE * WSTRIDE];   // 2 x 10240
    __shared__ int8_t sX8[2][M_DIM * WSTRIDE];   // 2 x  5120
    __shared__ float  sWS[2][NTILE * 4];         // 2 x  2048 (4 blocks/chunk)
    __shared__ float  sXS[2][M_DIM * 4];         // 2 x  1024

    const int tid  = threadIdx.x;
    const int lane = tid & 31;
    const int warp = tid >> 5;
    const int bn   = blockIdx.x;
    const int k0   = blockIdx.y * (K_DIM / KSPLIT);
    const int ilut = c_ilut[lane & 15];

    float acc[8][4];
    #pragma unroll
    for (int j = 0; j < 8; ++j)
        #pragma unroll
        for (int q = 0; q < 4; ++q) acc[j][q] = 0.f;

    // staging registers for one K-chunk (KC=64 = 4 scale blocks)
    int4  wc[8];    // 128 rows x 64 k codes / 256 thr
    uint4 xc;       // 64 rows x 64 int8 / 256 thr = 16 B
    float wsv[2];   // 128 rows x 4 blocks / 256 thr
    float xsv;      // 64 rows x 4 blocks / 256 thr

    #define LOAD_STAGE(it)                                                         \
    {                                                                              \
        const int kb = k0 + (it) * KC;                                             \
        _Pragma("unroll")                                                          \
        for (int t = 0; t < 8; ++t) {                                              \
            int p = tid + t * 256;                                                 \
            int row = p >> 4, kc4 = p & 15;                                        \
            wc[t] = *(const int4*)(w + (long)(bn * NTILE + row) * K_DIM            \
                                     + kb + kc4 * 4);                              \
        }                                                                          \
        {                                                                          \
            int row = tid >> 2, seg = tid & 3;                                     \
            xc = *(const uint4*)(g_xi8 + row * K_DIM + kb + seg * 16);             \
        }                                                                          \
        _Pragma("unroll")                                                          \
        for (int t = 0; t < 2; ++t) {                                              \
            int idx = tid + t * 256;                                               \
            int row = idx >> 2, b = idx & 3;                                       \
            wsv[t] = wsc[(bn * NTILE + row) * (K_DIM / KBLK) + (kb >> 4) + b];     \
        }                                                                          \
        {                                                                          \
            int row = tid >> 2, b = tid & 3;                                       \
            xsv = xsc[row * (K_DIM / KBLK) + (kb >> 4) + b];                       \
        }                                                                          \
    }

    #define STORE_STAGE(buf)                                                      \
    {                                                                              \
        _Pragma("unroll")                                                          \
        for (int t = 0; t < 8; ++t) {                                              \
            int p = tid + t * 256;                                                 \
            int row = p >> 4, kc4 = p & 15;                                        \
            int v0 = __shfl_sync(0xffffffffu, ilut, wc[t].x & 15);                 \
            int v1 = __shfl_sync(0xffffffffu, ilut, wc[t].y & 15);                 \
            int v2 = __shfl_sync(0xffffffffu, ilut, wc[t].z & 15);                 \
            int v3 = __shfl_sync(0xffffffffu, ilut, wc[t].w & 15);                 \
            unsigned t01 = __byte_perm((unsigned)v0, (unsigned)v1, 0x0040);        \
            unsigned t23 = __byte_perm((unsigned)v2, (unsigned)v3, 0x0040);        \
            *(unsigned*)(&sW8[buf][row * WSTRIDE + kc4 * 4]) =                     \
                __byte_perm(t01, t23, 0x5410);                                     \
        }                                                                          \
        {                                                                          \
            int row = tid >> 2, seg = tid & 3;                                     \
            *(uint4*)(&sX8[buf][row * WSTRIDE + seg * 16]) = xc;                   \
        }                                                                          \
        _Pragma("unroll")                                                          \
        for (int t = 0; t < 2; ++t) {                                              \
            int idx = tid + t * 256;                                               \
            sWS[buf][idx] = wsv[t];                                                \
        }                                                                          \
        sXS[buf][tid] = xsv;                                                       \
    }

    const int g  = lane >> 2;
    const int tg = lane & 3;

    LOAD_STAGE(0);

    for (int it = 0; it < ITERS; ++it) {
        const int buf = it & 1;
        STORE_STAGE(buf);
        __syncthreads();
        if (it + 1 < ITERS) LOAD_STAGE(it + 1);

        const int8_t* Wb = &sW8[buf][warp * 16 * WSTRIDE];
        const int8_t* Xb = &sX8[buf][0];

        // A fragments for all 4 k-blocks of this chunk
        unsigned a0[4], a1[4];
        #pragma unroll
        for (int b = 0; b < 4; ++b) {
            a0[b] = *(const unsigned*)(Wb + (g    ) * WSTRIDE + b * 16 + tg * 4);
            a1[b] = *(const unsigned*)(Wb + (g + 8) * WSTRIDE + b * 16 + tg * 4);
        }
        float4 wg4  = *(const float4*)&sWS[buf][(warp * 16 + g    ) * 4];
        float4 wg84 = *(const float4*)&sWS[buf][(warp * 16 + g + 8) * 4];
        float wsg [4] = {wg4.x,  wg4.y,  wg4.z,  wg4.w };
        float wsg8[4] = {wg84.x, wg84.y, wg84.z, wg84.w};

        #pragma unroll
        for (int j = 0; j < 8; ++j) {
            float4 xA4 = *(const float4*)&sXS[buf][(j * 8 + 2 * tg    ) * 4];
            float4 xB4 = *(const float4*)&sXS[buf][(j * 8 + 2 * tg + 1) * 4];
            float xsA[4] = {xA4.x, xA4.y, xA4.z, xA4.w};
            float xsB[4] = {xB4.x, xB4.y, xB4.z, xB4.w};
            #pragma unroll
            for (int b = 0; b < 4; ++b) {
                unsigned bf = *(const unsigned*)(Xb + (j * 8 + g) * WSTRIDE
                                                 + b * 16 + tg * 4);
                int d0, d1, d2, d3;
                asm volatile(
                    "mma.sync.aligned.m16n8k16.row.col.s32.s8.s8.s32 "
                    "{%0,%1,%2,%3}, {%4,%5}, {%6}, {%7,%8,%9,%10};\n"
                    : "=r"(d0), "=r"(d1), "=r"(d2), "=r"(d3)
                    : "r"(a0[b]), "r"(a1[b]), "r"(bf),
                      "r"(0), "r"(0), "r"(0), "r"(0));
                // exact int->float (|d| <= 2304 << 2^22) via magic constant
                float f0 = __int_as_float(d0 + 0x4B400000) - 12582912.0f;
                float f1 = __int_as_float(d1 + 0x4B400000) - 12582912.0f;
                float f2 = __int_as_float(d2 + 0x4B400000) - 12582912.0f;
                float f3 = __int_as_float(d3 + 0x4B400000) - 12582912.0f;
                acc[j][0] = fmaf(f0, wsg [b] * xsA[b], acc[j][0]);
                acc[j][1] = fmaf(f1, wsg [b] * xsB[b], acc[j][1]);
                acc[j][2] = fmaf(f2, wsg8[b] * xsA[b], acc[j][2]);
                acc[j][3] = fmaf(f3, wsg8[b] * xsB[b], acc[j][3]);
            }
        }
    }

    // ---- epilogue: plain stores to this split's private slab ----
    float* S = g_scratch4 + blockIdx.y * (M_DIM * N_DIM);
    const int nbase = bn * NTILE + warp * 16 + g;
    #pragma unroll
    for (int j = 0; j < 8; ++j) {
        const int m0 = j * 8 + tg * 2;
        S[(m0    ) * N_DIM + nbase    ] = acc[j][0];
        S[(m0 + 1) * N_DIM + nbase    ] = acc[j][1];
        S[(m0    ) * N_DIM + nbase + 8] = acc[j][2];
        S[(m0 + 1) * N_DIM + nbase + 8] = acc[j][3];
    }
    #undef LOAD_STAGE
    #undef STORE_STAGE
}

// ---------------------------------------------------------------------------
// Kernel C: out (fp32 buffer) = fp32(bf16(sum_slabs * gx*gw*0.25 + bias[n]))
// 0.25 compensates the 2x-int LUT on both operands.
// ---------------------------------------------------------------------------
__global__ void finalize_kernel(const float* __restrict__ g1,
                                const float* __restrict__ g2,
                                const float* __restrict__ bias,
                                float* __restrict__ out) {
    int idx = blockIdx.x * blockDim.x + threadIdx.x;
    if (idx >= M_DIM * N_DIM) return;
    const float g = g1[0] * g2[0] * 0.25f;
    const int n = idx & (N_DIM - 1);
    float s = g_scratch4[idx]
            + g_scratch4[idx + 1 * M_DIM * N_DIM]
            + g_scratch4[idx + 2 * M_DIM * N_DIM]
            + g_scratch4[idx + 3 * M_DIM * N_DIM];
    float v = fmaf(s, g, bias[n]);
    out[idx] = __bfloat162float(__float2bfloat16(v));
}

// ---------------------------------------------------------------------------
// Inputs identified by element count (all distinct; byte-count fallback).
// ---------------------------------------------------------------------------
extern "C" void kernel_launch(void* const* d_in, const int* in_sizes, int n_in,
                              void* d_out, int out_size) {
    const int*   x    = nullptr;
    const float* xs   = nullptr;
    const int*   wgt  = nullptr;
    const float* wsc  = nullptr;
    const float* bias = nullptr;
    const float* gA   = nullptr;
    const float* gB   = nullptr;

    for (int pass = 0; pass < 2 && !wgt; ++pass) {
        const int mul = (pass == 0) ? 1 : 4;
        x = nullptr; xs = nullptr; wgt = nullptr; wsc = nullptr;
        bias = nullptr; gA = nullptr; gB = nullptr;
        for (int i = 0; i < n_in; ++i) {
            long sz = (long)in_sizes[i];
            if      (sz == (long)M_DIM * K_DIM * mul)          x    = (const int*)  d_in[i];
            else if (sz == (long)M_DIM * (K_DIM/KBLK) * mul)   xs   = (const float*)d_in[i];
            else if (sz == (long)N_DIM * K_DIM * mul)          wgt  = (const int*)  d_in[i];
            else if (sz == (long)N_DIM * (K_DIM/KBLK) * mul)   wsc  = (const float*)d_in[i];
            else if (sz == (long)N_DIM * mul)                  bias = (const float*)d_in[i];
            else if (sz == 1 * mul) { if (!gA) gA = (const float*)d_in[i];
                                      else     gB = (const float*)d_in[i]; }
        }
    }

    prep_kernel<<<(M_DIM * K_DIM / 4) / THREADS, THREADS>>>(x);
    gemm_kernel<<<dim3(N_DIM / NTILE, KSPLIT), THREADS>>>(wgt, wsc, xs);
    finalize_kernel<<<(M_DIM * N_DIM) / 256, 256>>>(gA, gB, bias,
                                                    (float*)d_out);
}

// round 9
// speedup vs baseline: 2.1348x; 1.0306x over previous
#include <cuda_runtime.h>
#include <cuda_bf16.h>
#include <cstdint>

#define M_DIM 64
#define K_DIM 8192
#define N_DIM 8192
#define KBLK  16
#define NTILE 128
#define KSPLIT 8
#define KC    32
#define ITERS ((K_DIM / KSPLIT) / KC)   /* 32 */
#define THREADS 256
#define WSTRIDE 48   /* int8 row stride: 32 data + 16 pad -> conflict-free frags */

__device__ float  g_scratch8[KSPLIT * M_DIM * N_DIM];  // 16 MB fp32 partial slabs
__device__ int8_t g_xi8[M_DIM * K_DIM];                // 512 KB: x as int8 (2x values)

// 2x NVFP4 LUT as integers (sign folded): exact in int8.
__constant__ int c_ilut[16] = { 0, 1, 2, 3, 4, 6, 8, 12,
                                0,-1,-2,-3,-4,-6,-8,-12};

#define MAGIC_I 0x4B400000
#define MAGIC_F 12582912.0f

// ---------------------------------------------------------------------------
// Kernel A: x codes -> int8 (2x value). 4 codes per thread via shfl-LUT.
// ---------------------------------------------------------------------------
__global__ void prep_kernel(const int* __restrict__ x) {
    int t    = blockIdx.x * blockDim.x + threadIdx.x;   // < M*K/4
    int lane = threadIdx.x & 31;
    int ilut = c_ilut[lane & 15];
    int4 c = ((const int4*)x)[t];
    int v0 = __shfl_sync(0xffffffffu, ilut, c.x & 15);
    int v1 = __shfl_sync(0xffffffffu, ilut, c.y & 15);
    int v2 = __shfl_sync(0xffffffffu, ilut, c.z & 15);
    int v3 = __shfl_sync(0xffffffffu, ilut, c.w & 15);
    unsigned t01 = __byte_perm((unsigned)v0, (unsigned)v1, 0x0040);
    unsigned t23 = __byte_perm((unsigned)v2, (unsigned)v3, 0x0040);
    ((unsigned*)g_xi8)[t] = __byte_perm(t01, t23, 0x5410);
}

// ---------------------------------------------------------------------------
// Kernel B: exact int8 IMMA GEMM, per-16-block fp32 dequant in packed f32x2.
// Grid (N/128, KSPLIT). CTA 256 thr / 8 warps; warp w owns weight rows
// [w*16, w*16+16) x all 64 x rows. Fragment & output mappings identical to
// the round-7 passing kernel.
// ---------------------------------------------------------------------------
__global__ void __launch_bounds__(THREADS, 2)
gemm_kernel(const int* __restrict__ w, const float* __restrict__ wsc,
            const float* __restrict__ xsc) {
    __shared__ int8_t sW8[2][NTILE * WSTRIDE];   // 2 x 6144
    __shared__ int8_t sX8[2][M_DIM * WSTRIDE];   // 2 x 3072
    __shared__ float  sWS[2][2][NTILE];          // per (buf, block b, w-row)
    __shared__ float  sXS[2][2][M_DIM];          // per (buf, block b, x-row)

    const int tid  = threadIdx.x;
    const int lane = tid & 31;
    const int warp = tid >> 5;
    const int bn   = blockIdx.x;
    const int k0   = blockIdx.y * (K_DIM / KSPLIT);
    const int ilut = c_ilut[lane & 15];

    // packed accumulators: accp[j][0]=(c0,c1), accp[j][1]=(c2,c3)
    unsigned long long accp[8][2];
    #pragma unroll
    for (int j = 0; j < 8; ++j) { accp[j][0] = 0ull; accp[j][1] = 0ull; }

    // staging registers for one K-chunk (KC=32 = 2 scale blocks)
    int4  wc[4];    // 128 rows x 32 k codes / 256 thr
    uint2 xc;       // 64 rows x 32 int8 / 256 thr = 8 B
    float wsv;      // 128 rows x 2 blocks / 256 thr
    float xsv;      // 64 rows x 2 blocks / 128 thr

    #define LOAD_STAGE(it)                                                         \
    {                                                                              \
        const int kb = k0 + (it) * KC;                                             \
        _Pragma("unroll")                                                          \
        for (int t = 0; t < 4; ++t) {                                              \
            int p = tid + t * 256;                                                 \
            int row = p >> 3, kc4 = p & 7;                                         \
            wc[t] = *(const int4*)(w + (long)(bn * NTILE + row) * K_DIM            \
                                     + kb + kc4 * 4);                              \
        }                                                                          \
        {                                                                          \
            int row = tid >> 2, seg = tid & 3;                                     \
            xc = *(const uint2*)(g_xi8 + row * K_DIM + kb + seg * 8);              \
        }                                                                          \
        {                                                                          \
            int row = tid >> 1, b = tid & 1;                                       \
            wsv = wsc[(bn * NTILE + row) * (K_DIM / KBLK) + (kb >> 4) + b];        \
        }                                                                          \
        if (tid < 128) {                                                           \
            int row = tid >> 1, b = tid & 1;                                       \
            xsv = xsc[row * (K_DIM / KBLK) + (kb >> 4) + b];                       \
        }                                                                          \
    }

    #define STORE_STAGE(buf)                                                      \
    {                                                                              \
        _Pragma("unroll")                                                          \
        for (int t = 0; t < 4; ++t) {                                              \
            int p = tid + t * 256;                                                 \
            int row = p >> 3, kc4 = p & 7;                                         \
            int v0 = __shfl_sync(0xffffffffu, ilut, wc[t].x & 15);                 \
            int v1 = __shfl_sync(0xffffffffu, ilut, wc[t].y & 15);                 \
            int v2 = __shfl_sync(0xffffffffu, ilut, wc[t].z & 15);                 \
            int v3 = __shfl_sync(0xffffffffu, ilut, wc[t].w & 15);                 \
            unsigned t01 = __byte_perm((unsigned)v0, (unsigned)v1, 0x0040);        \
            unsigned t23 = __byte_perm((unsigned)v2, (unsigned)v3, 0x0040);        \
            *(unsigned*)(&sW8[buf][row * WSTRIDE + kc4 * 4]) =                     \
                __byte_perm(t01, t23, 0x5410);                                     \
        }                                                                          \
        {                                                                          \
            int row = tid >> 2, seg = tid & 3;                                     \
            *(uint2*)(&sX8[buf][row * WSTRIDE + seg * 8]) = xc;                    \
        }                                                                          \
        {                                                                          \
            int row = tid >> 1, b = tid & 1;                                       \
            sWS[buf][b][row] = wsv;                                                \
        }                                                                          \
        if (tid < 128) {                                                           \
            int row = tid >> 1, b = tid & 1;                                       \
            sXS[buf][b][row] = xsv;                                                \
        }                                                                          \
    }

    const int g  = lane >> 2;
    const int tg = lane & 3;

    LOAD_STAGE(0);

    for (int it = 0; it < ITERS; ++it) {
        const int buf = it & 1;
        STORE_STAGE(buf);
        __syncthreads();
        if (it + 1 < ITERS) LOAD_STAGE(it + 1);

        const int8_t* Wb = &sW8[buf][warp * 16 * WSTRIDE];
        const int8_t* Xb = &sX8[buf][0];

        // per-chunk hoists: A fragments + duplicated W scales (per block b)
        unsigned a0[2], a1[2];
        unsigned long long wdup[2], w8dup[2];
        #pragma unroll
        for (int b = 0; b < 2; ++b) {
            a0[b] = *(const unsigned*)(Wb + (g    ) * WSTRIDE + b * 16 + tg * 4);
            a1[b] = *(const unsigned*)(Wb + (g + 8) * WSTRIDE + b * 16 + tg * 4);
            float wsg  = sWS[buf][b][warp * 16 + g    ];
            float wsg8 = sWS[buf][b][warp * 16 + g + 8];
            asm("mov.b64 %0, {%1, %1};" : "=l"(wdup[b])  : "r"(__float_as_uint(wsg)));
            asm("mov.b64 %0, {%1, %1};" : "=l"(w8dup[b]) : "r"(__float_as_uint(wsg8)));
        }

        unsigned long long magic2;
        asm("mov.b64 %0, {%1, %1};" : "=l"(magic2) : "f"(-MAGIC_F));

        #pragma unroll
        for (int j = 0; j < 8; ++j) {
            #pragma unroll
            for (int b = 0; b < 2; ++b) {
                // packed (xsA, xsB): adjacent x-rows (2tg, 2tg+1) in sXS
                unsigned long long xsp =
                    *(const unsigned long long*)&sXS[buf][b][j * 8 + 2 * tg];
                unsigned bf = *(const unsigned*)(Xb + (j * 8 + g) * WSTRIDE
                                                 + b * 16 + tg * 4);
                int d0, d1, d2, d3;
                asm volatile(
                    "mma.sync.aligned.m16n8k16.row.col.s32.s8.s8.s32 "
                    "{%0,%1,%2,%3}, {%4,%5}, {%6}, {%7,%8,%9,%10};\n"
                    : "=r"(d0), "=r"(d1), "=r"(d2), "=r"(d3)
                    : "r"(a0[b]), "r"(a1[b]), "r"(bf),
                      "r"(0), "r"(0), "r"(0), "r"(0));

                unsigned long long sc01, sc23, p01, p23, f01, f23;
                asm("mul.rn.f32x2 %0, %1, %2;" : "=l"(sc01) : "l"(xsp), "l"(wdup[b]));
                asm("mul.rn.f32x2 %0, %1, %2;" : "=l"(sc23) : "l"(xsp), "l"(w8dup[b]));
                // exact int -> float via magic bias (|d| <= 2304 << 2^22)
                asm("mov.b64 %0, {%1, %2};" : "=l"(p01)
                    : "r"(d0 + MAGIC_I), "r"(d1 + MAGIC_I));
                asm("mov.b64 %0, {%1, %2};" : "=l"(p23)
                    : "r"(d2 + MAGIC_I), "r"(d3 + MAGIC_I));
                asm("add.rn.f32x2 %0, %1, %2;" : "=l"(f01) : "l"(p01), "l"(magic2));
                asm("add.rn.f32x2 %0, %1, %2;" : "=l"(f23) : "l"(p23), "l"(magic2));
                asm("fma.rn.f32x2 %0, %1, %2, %0;" : "+l"(accp[j][0])
                    : "l"(f01), "l"(sc01));
                asm("fma.rn.f32x2 %0, %1, %2, %0;" : "+l"(accp[j][1])
                    : "l"(f23), "l"(sc23));
            }
        }
    }

    // ---- epilogue: plain stores to this split's private slab ----
    float* S = g_scratch8 + blockIdx.y * (M_DIM * N_DIM);
    const int nbase = bn * NTILE + warp * 16 + g;
    #pragma unroll
    for (int j = 0; j < 8; ++j) {
        const int m0 = j * 8 + tg * 2;
        unsigned c0, c1, c2, c3;
        asm("mov.b64 {%0, %1}, %2;" : "=r"(c0), "=r"(c1) : "l"(accp[j][0]));
        asm("mov.b64 {%0, %1}, %2;" : "=r"(c2), "=r"(c3) : "l"(accp[j][1]));
        S[(m0    ) * N_DIM + nbase    ] = __uint_as_float(c0);
        S[(m0 + 1) * N_DIM + nbase    ] = __uint_as_float(c1);
        S[(m0    ) * N_DIM + nbase + 8] = __uint_as_float(c2);
        S[(m0 + 1) * N_DIM + nbase + 8] = __uint_as_float(c3);
    }
    #undef LOAD_STAGE
    #undef STORE_STAGE
}

// ---------------------------------------------------------------------------
// Kernel C: out (fp32 buffer) = fp32(bf16(sum_slabs * gx*gw*0.25 + bias[n]))
// 0.25 compensates the 2x-int LUT on both operands.
// ---------------------------------------------------------------------------
__global__ void finalize_kernel(const float* __restrict__ g1,
                                const float* __restrict__ g2,
                                const float* __restrict__ bias,
                                float* __restrict__ out) {
    int idx = blockIdx.x * blockDim.x + threadIdx.x;
    if (idx >= M_DIM * N_DIM) return;
    const float g = g1[0] * g2[0] * 0.25f;
    const int n = idx & (N_DIM - 1);
    float s = 0.f;
    #pragma unroll
    for (int t = 0; t < KSPLIT; ++t)
        s += g_scratch8[idx + t * (M_DIM * N_DIM)];
    float v = fmaf(s, g, bias[n]);
    out[idx] = __bfloat162float(__float2bfloat16(v));
}

// ---------------------------------------------------------------------------
// Inputs identified by element count (all distinct; byte-count fallback).
// ---------------------------------------------------------------------------
extern "C" void kernel_launch(void* const* d_in, const int* in_sizes, int n_in,
                              void* d_out, int out_size) {
    const int*   x    = nullptr;
    const float* xs   = nullptr;
    const int*   wgt  = nullptr;
    const float* wsc  = nullptr;
    const float* bias = nullptr;
    const float* gA   = nullptr;
    const float* gB   = nullptr;

    for (int pass = 0; pass < 2 && !wgt; ++pass) {
        const int mul = (pass == 0) ? 1 : 4;
        x = nullptr; xs = nullptr; wgt = nullptr; wsc = nullptr;
        bias = nullptr; gA = nullptr; gB = nullptr;
        for (int i = 0; i < n_in; ++i) {
            long sz = (long)in_sizes[i];
            if      (sz == (long)M_DIM * K_DIM * mul)          x    = (const int*)  d_in[i];
            else if (sz == (long)M_DIM * (K_DIM/KBLK) * mul)   xs   = (const float*)d_in[i];
            else if (sz == (long)N_DIM * K_DIM * mul)          wgt  = (const int*)  d_in[i];
            else if (sz == (long)N_DIM * (K_DIM/KBLK) * mul)   wsc  = (const float*)d_in[i];
            else if (sz == (long)N_DIM * mul)                  bias = (const float*)d_in[i];
            else if (sz == 1 * mul) { if (!gA) gA = (const float*)d_in[i];
                                      else     gB = (const float*)d_in[i]; }
        }
    }

    prep_kernel<<<(M_DIM * K_DIM / 4) / THREADS, THREADS>>>(x);
    gemm_kernel<<<dim3(N_DIM / NTILE, KSPLIT), THREADS>>>(wgt, wsc, xs);
    finalize_kernel<<<(M_DIM * N_DIM) / 256, 256>>>(gA, gB, bias,
                                                    (float*)d_out);
}